// round 13
// baseline (speedup 1.0000x reference)
#include <cuda_runtime.h>
#include <cuda_bf16.h>
#include <cstdint>

// NeRF emission-absorption raymarcher — FINAL (full config matrix explored).
// Inputs (metadata order):
//   d_in[0]: rays_densities (B,R,N,1) float32   -> B*R*N elems
//   d_in[1]: rays_features  (B,R,N,F) float32   -> B*R*N*F elems
//   d_in[2]: lengths        (B,R,N)   float32   -> B*R*N elems
// Output: (B,R,F+1) float32, F=3 -> 4 floats per ray.
//
// One warp per ray. Lane i owns samples [4i, 4i+4). All loads are float4,
// consecutive lanes -> consecutive 16B -> fully coalesced. Streaming (.cs)
// + L2::256B prefetch on all loads; streaming store. Warp shuffle
// product-scan for the shifted cumprod; shuffle-tree reductions for outputs.
//
// 12-round session summary: HBM-bound at the 337 MB traffic floor,
// 6.6-6.8 TB/s sustained (84-86% of spec = this chip's stream ceiling);
// L2/issue/fma/tensor all slack. Full config matrix benched:
//   .cs hints        +3%   (kept)
//   L2::256B prefetch noise-neutral, best median kernel time (kept)
//   128t vs 256t CTAs neutral; 128t holds the wall minimum 51.68 us (kept)
//   persistent 2x-buffer -11% (rejected: occupancy IS the MLP engine)
//   reduction-tree fold   neutral (not needed)
// Kernel 50.1-51.3 us across 9 profiles; converged optimum.

#define EPS 1e-10f

// float4 streaming load with L2 256B prefetch hint
__device__ __forceinline__ float4 ldcs_pf256(const float4* p)
{
    float4 v;
    asm volatile("ld.global.cs.L2::256B.v4.f32 {%0, %1, %2, %3}, [%4];"
                 : "=f"(v.x), "=f"(v.y), "=f"(v.z), "=f"(v.w)
                 : "l"(p));
    return v;
}

__global__ __launch_bounds__(128, 16)
void ea_raymarch_kernel(const float* __restrict__ dens,
                        const float* __restrict__ feat,
                        const float* __restrict__ lens,
                        float* __restrict__ out,
                        int n_rays)
{
    const int warps_per_block = blockDim.x >> 5;
    const int ray = blockIdx.x * warps_per_block + (threadIdx.x >> 5);
    if (ray >= n_rays) return;
    const int lane = threadIdx.x & 31;

    // N = 128, F = 3 (fixed shapes for this problem)
    const long long base_n  = (long long)ray * 128;      // densities / lengths base (floats)
    const long long base_f  = (long long)ray * 384;      // features base (floats)

    // ---- loads: streaming + L2 256B prefetch ----
    const float4 d4 = ldcs_pf256((const float4*)(dens + base_n) + lane);
    const float4 l4 = ldcs_pf256((const float4*)(lens + base_n) + lane);
    const float4* fptr = (const float4*)(feat + base_f) + 3 * lane;
    const float4 f4a = ldcs_pf256(fptr + 0);   // s0.xyz, s1.x
    const float4 f4b = ldcs_pf256(fptr + 1);   // s1.yz,  s2.xy
    const float4 f4c = ldcs_pf256(fptr + 2);   // s2.z,   s3.xyz

    // a_k = 1 + EPS - d_k
    const float a0 = 1.0f + EPS - d4.x;
    const float a1 = 1.0f + EPS - d4.y;
    const float a2 = 1.0f + EPS - d4.z;
    const float a3 = 1.0f + EPS - d4.w;

    // warp inclusive product scan of per-lane total product
    float incl = (a0 * a1) * (a2 * a3);
    #pragma unroll
    for (int off = 1; off < 32; off <<= 1) {
        float v = __shfl_up_sync(0xffffffffu, incl, off);
        if (lane >= off) incl *= v;
    }
    // exclusive: shift by one lane
    float excl = __shfl_up_sync(0xffffffffu, incl, 1);
    if (lane == 0) excl = 1.0f;

    // per-sample absorptions and weights
    const float ab0 = excl;
    const float ab1 = ab0 * a0;
    const float ab2 = ab1 * a1;
    const float ab3 = ab2 * a2;

    const float w0 = d4.x * ab0;
    const float w1 = d4.y * ab1;
    const float w2 = d4.z * ab2;
    const float w3 = d4.w * ab3;

    // feature channel unpack per sample:
    // s0: (f4a.x, f4a.y, f4a.z)   s1: (f4a.w, f4b.x, f4b.y)
    // s2: (f4b.z, f4b.w, f4c.x)   s3: (f4c.y, f4c.z, f4c.w)
    float r = w0 * f4a.x + w1 * f4a.w + w2 * f4b.z + w3 * f4c.y;
    float g = w0 * f4a.y + w1 * f4b.x + w2 * f4b.w + w3 * f4c.z;
    float b = w0 * f4a.z + w1 * f4b.y + w2 * f4c.x + w3 * f4c.w;

    float depth = w0 * l4.x + w1 * l4.y + w2 * l4.z + w3 * l4.w;
    float alpha = (w0 + w1) + (w2 + w3);

    // warp reductions (sum) for the 5 accumulators
    #pragma unroll
    for (int off = 16; off > 0; off >>= 1) {
        r     += __shfl_down_sync(0xffffffffu, r,     off);
        g     += __shfl_down_sync(0xffffffffu, g,     off);
        b     += __shfl_down_sync(0xffffffffu, b,     off);
        depth += __shfl_down_sync(0xffffffffu, depth, off);
        alpha += __shfl_down_sync(0xffffffffu, alpha, off);
    }

    // last length along the ray = lane 31's l4.w
    const float last_len = __shfl_sync(0xffffffffu, l4.w, 31);

    if (lane == 0) {
        const float one_m_alpha = 1.0f - alpha;
        float4 o;
        o.x = r + one_m_alpha;                 // WHITE_BG
        o.y = g + one_m_alpha;
        o.z = b + one_m_alpha;
        o.w = depth + one_m_alpha * last_len;  // background depth fill
        __stcs((float4*)out + ray, o);
    }
}

extern "C" void kernel_launch(void* const* d_in, const int* in_sizes, int n_in,
                              void* d_out, int out_size)
{
    const float* dens = (const float*)d_in[0];
    const float* feat = (const float*)d_in[1];
    const float* lens = (const float*)d_in[2];
    float* out = (float*)d_out;

    // out_size = n_rays * (F+1) = n_rays * 4
    const int n_rays = out_size / 4;          // 131072 for this problem

    const int threads = 128;                  // 4 warps/block
    const int warps_per_block = threads / 32;
    const int blocks = (n_rays + warps_per_block - 1) / warps_per_block;

    ea_raymarch_kernel<<<blocks, threads>>>(dens, feat, lens, out, n_rays);
}

// round 14
// speedup vs baseline: 1.0696x; 1.0696x over previous
#include <cuda_runtime.h>
#include <cuda_bf16.h>
#include <cstdint>

// NeRF emission-absorption raymarcher — FINAL: plain streaming config.
// Inputs (metadata order):
//   d_in[0]: rays_densities (B,R,N,1) float32   -> B*R*N elems
//   d_in[1]: rays_features  (B,R,N,F) float32   -> B*R*N*F elems
//   d_in[2]: lengths        (B,R,N)   float32   -> B*R*N elems
// Output: (B,R,F+1) float32, F=3 -> 4 floats per ray.
//
// One warp per ray. Lane i owns samples [4i, 4i+4). All loads are float4,
// consecutive lanes -> consecutive 16B -> fully coalesced, streaming
// (evict-first, __ldcs) policy; streaming store. Warp shuffle product-scan
// for the shifted cumprod; shuffle-tree reductions for the 5 outputs.
//
// R14 verdict: plain .cs beats .cs+L2::256B-prefetch ON WALL CLOCK —
// 3/3 runs at the 51.68 us floor vs 0/7 for prefetch (median 52.8).
// Prefetch's extra L2 sector requests cost under the steady-state graph-
// replay loop despite looking neutral in single-shot ncu captures.
// Session model (13 rounds, 10 profiles): HBM-bound at the 337 MB traffic
// floor, 6.6-6.8 TB/s (84-86% of spec = stream ceiling); persistent
// buffering rejected (-11%, occupancy is the MLP engine); CTA size and
// reduction-count neutral. This configuration is the converged optimum.

#define EPS 1e-10f

__global__ __launch_bounds__(128, 16)
void ea_raymarch_kernel(const float* __restrict__ dens,
                        const float* __restrict__ feat,
                        const float* __restrict__ lens,
                        float* __restrict__ out,
                        int n_rays)
{
    const int warps_per_block = blockDim.x >> 5;
    const int ray = blockIdx.x * warps_per_block + (threadIdx.x >> 5);
    if (ray >= n_rays) return;
    const int lane = threadIdx.x & 31;

    // N = 128, F = 3 (fixed shapes for this problem)
    const long long base_n  = (long long)ray * 128;      // densities / lengths base (floats)
    const long long base_f  = (long long)ray * 384;      // features base (floats)

    // ---- loads: streaming (evict-first) ----
    const float4 d4 = __ldcs((const float4*)(dens + base_n) + lane);
    const float4 l4 = __ldcs((const float4*)(lens + base_n) + lane);
    const float4* fptr = (const float4*)(feat + base_f) + 3 * lane;
    const float4 f4a = __ldcs(fptr + 0);   // s0.xyz, s1.x
    const float4 f4b = __ldcs(fptr + 1);   // s1.yz,  s2.xy
    const float4 f4c = __ldcs(fptr + 2);   // s2.z,   s3.xyz

    // a_k = 1 + EPS - d_k
    const float a0 = 1.0f + EPS - d4.x;
    const float a1 = 1.0f + EPS - d4.y;
    const float a2 = 1.0f + EPS - d4.z;
    const float a3 = 1.0f + EPS - d4.w;

    // warp inclusive product scan of per-lane total product
    float incl = (a0 * a1) * (a2 * a3);
    #pragma unroll
    for (int off = 1; off < 32; off <<= 1) {
        float v = __shfl_up_sync(0xffffffffu, incl, off);
        if (lane >= off) incl *= v;
    }
    // exclusive: shift by one lane
    float excl = __shfl_up_sync(0xffffffffu, incl, 1);
    if (lane == 0) excl = 1.0f;

    // per-sample absorptions and weights
    const float ab0 = excl;
    const float ab1 = ab0 * a0;
    const float ab2 = ab1 * a1;
    const float ab3 = ab2 * a2;

    const float w0 = d4.x * ab0;
    const float w1 = d4.y * ab1;
    const float w2 = d4.z * ab2;
    const float w3 = d4.w * ab3;

    // feature channel unpack per sample:
    // s0: (f4a.x, f4a.y, f4a.z)   s1: (f4a.w, f4b.x, f4b.y)
    // s2: (f4b.z, f4b.w, f4c.x)   s3: (f4c.y, f4c.z, f4c.w)
    float r = w0 * f4a.x + w1 * f4a.w + w2 * f4b.z + w3 * f4c.y;
    float g = w0 * f4a.y + w1 * f4b.x + w2 * f4b.w + w3 * f4c.z;
    float b = w0 * f4a.z + w1 * f4b.y + w2 * f4c.x + w3 * f4c.w;

    float depth = w0 * l4.x + w1 * l4.y + w2 * l4.z + w3 * l4.w;
    float alpha = (w0 + w1) + (w2 + w3);

    // warp reductions (sum) for the 5 accumulators
    #pragma unroll
    for (int off = 16; off > 0; off >>= 1) {
        r     += __shfl_down_sync(0xffffffffu, r,     off);
        g     += __shfl_down_sync(0xffffffffu, g,     off);
        b     += __shfl_down_sync(0xffffffffu, b,     off);
        depth += __shfl_down_sync(0xffffffffu, depth, off);
        alpha += __shfl_down_sync(0xffffffffu, alpha, off);
    }

    // last length along the ray = lane 31's l4.w
    const float last_len = __shfl_sync(0xffffffffu, l4.w, 31);

    if (lane == 0) {
        const float one_m_alpha = 1.0f - alpha;
        float4 o;
        o.x = r + one_m_alpha;                 // WHITE_BG
        o.y = g + one_m_alpha;
        o.z = b + one_m_alpha;
        o.w = depth + one_m_alpha * last_len;  // background depth fill
        __stcs((float4*)out + ray, o);
    }
}

extern "C" void kernel_launch(void* const* d_in, const int* in_sizes, int n_in,
                              void* d_out, int out_size)
{
    const float* dens = (const float*)d_in[0];
    const float* feat = (const float*)d_in[1];
    const float* lens = (const float*)d_in[2];
    float* out = (float*)d_out;

    // out_size = n_rays * (F+1) = n_rays * 4
    const int n_rays = out_size / 4;          // 131072 for this problem

    const int threads = 128;                  // 4 warps/block
    const int warps_per_block = threads / 32;
    const int blocks = (n_rays + warps_per_block - 1) / warps_per_block;

    ea_raymarch_kernel<<<blocks, threads>>>(dens, feat, lens, out, n_rays);
}